// round 9
// baseline (speedup 1.0000x reference)
#include <cuda_runtime.h>
#include <cuda_bf16.h>

// Problem constants (fixed by the reference)
#define BB  4
#define LL  512
#define HH  768
#define SS  100
#define RR  100
#define EE  25
#define NEC 10              // entity classes
#define NRC 6               // relation classes
#define NEGV (-1e20f)

#define H4       (HH/4)         // 192 float4 lanes per hidden row
#define SPAN_DIM (HH + EE)      // 793
#define SPAN_PAD 800            // padded (mult of 4), zero tail
#define NENT     (BB*SS)        // 400
#define NREL     (BB*RR)        // 400
#define NPOOL    (NENT + NREL)  // 800
#define NROW     (NEC + 2*NRC)  // 22 projection rows per entity

// transpose workload: 22*800 + 6*768 = 22208 elements -> 87 blocks
#define NTRW     (NROW*SPAN_PAD + NRC*HH)
#define NTR      ((NTRW + 255) / 256)          // 87
#define GRID     (NTR + NPOOL)                 // 887

// Scratch (static device globals — no runtime allocation)
// wentT rows: [0,10) = w_span^T ; [10,16) = head-slice^T ; [16,22) = tail-slice^T
__device__ float g_wentT[NROW*SPAN_PAD];   // 22 x 800
__device__ float g_wctxT[NRC*HH];          // 6 x 768
__device__ float g_p1[NENT*NRC];           // head projections per entity
__device__ float g_p2[NENT*NRC];           // tail projections per entity
__device__ float g_pc[NREL*NRC];           // ctx projections per relation
__device__ int   g_wdone = 0;              // transpose-blocks-finished counter
__device__ int   g_pdone = 0;              // pool-blocks-finished counter

__global__ void __launch_bounds__(256)
spert_fused_kernel(const float* __restrict__ hid,
                   const int*   __restrict__ emask,
                   const int*   __restrict__ rel,
                   const int*   __restrict__ cmask,
                   const float* __restrict__ size_emb,
                   const float* __restrict__ w_span,
                   const float* __restrict__ b_span,
                   const float* __restrict__ w_rel,
                   const float* __restrict__ b_rel,
                   float*       __restrict__ out)
{
    const int bid = blockIdx.x;
    const int t   = threadIdx.x;

    // ================= transpose blocks (lowest bids -> wave 1) =================
    if (bid < NTR) {
        const int i = bid * 256 + t;
        if (i < NROW*SPAN_PAD) {
            const int row = i / SPAN_PAD, k = i - row*SPAN_PAD;
            float v = 0.f;
            if (row < NEC) {
                if (k < SPAN_DIM) v = w_span[k*NEC + row];
            } else if (row < NEC + NRC) {
                const int j = row - NEC;
                if      (k < HH)       v = w_rel[(HH + k)*NRC + j];
                else if (k < SPAN_DIM) v = w_rel[(3*HH + (k - HH))*NRC + j];
            } else {
                const int j = row - NEC - NRC;
                if      (k < HH)       v = w_rel[(2*HH + k)*NRC + j];
                else if (k < SPAN_DIM) v = w_rel[(3*HH + EE + (k - HH))*NRC + j];
            }
            g_wentT[i] = v;
        } else if (i - NROW*SPAN_PAD < NRC*HH) {
            const int i2 = i - NROW*SPAN_PAD;
            const int j = i2 / HH, k = i2 - j*HH;
            g_wctxT[i2] = w_rel[k*NRC + j];
        }
        __threadfence();
        __syncthreads();
        if (t == 0) atomicAdd(&g_wdone, 1);   // release
        return;
    }

    // ================= pool + project blocks =================
    __shared__ float sred[8][NROW];
    __shared__ int s_start, s_last;

    const int pbid = bid - NTR;              // 0..799
    const bool is_ent = (pbid < NENT);
    const int idx  = is_ent ? pbid : pbid - NENT;   // b*N + n
    const int b    = idx / SS;
    const int lane = t & 31, warp = t >> 5;

    // ---- recover contiguous span (start, len) ----
    const int* mrow = (is_ent ? emask : cmask) + (size_t)idx * LL;
    const int m0 = mrow[t];
    const int m1 = mrow[t + 256];
    if (t == 0) s_start = LL;
    __syncthreads();
    unsigned bal0 = __ballot_sync(0xffffffffu, m0 != 0);
    unsigned bal1 = __ballot_sync(0xffffffffu, m1 != 0);
    if (lane == 0) {
        if (bal0) atomicMin(&s_start, (warp << 5) + __ffs(bal0) - 1);
        if (bal1) atomicMin(&s_start, 256 + (warp << 5) + __ffs(bal1) - 1);
    }
    const int len = __syncthreads_count(m0 != 0) + __syncthreads_count(m1 != 0);
    const int start = s_start;

    // ---- masked max pool over span (float4, unroll 8) — weight-independent ----
    float4 rv = make_float4(0.f, 0.f, 0.f, 0.f);
    if (t < H4) {
        float4 mx = make_float4(NEGV, NEGV, NEGV, NEGV);
        const float4* hb = reinterpret_cast<const float4*>(hid + (size_t)b * LL * HH) + t;
        int l = start;
        const int e = start + len;
        for (; l + 8 <= e; l += 8) {
            float4 v0 = hb[(size_t)(l+0) * H4];
            float4 v1 = hb[(size_t)(l+1) * H4];
            float4 v2 = hb[(size_t)(l+2) * H4];
            float4 v3 = hb[(size_t)(l+3) * H4];
            float4 v4 = hb[(size_t)(l+4) * H4];
            float4 v5 = hb[(size_t)(l+5) * H4];
            float4 v6 = hb[(size_t)(l+6) * H4];
            float4 v7 = hb[(size_t)(l+7) * H4];
            mx.x = fmaxf(mx.x, fmaxf(fmaxf(fmaxf(v0.x, v1.x), fmaxf(v2.x, v3.x)),
                                     fmaxf(fmaxf(v4.x, v5.x), fmaxf(v6.x, v7.x))));
            mx.y = fmaxf(mx.y, fmaxf(fmaxf(fmaxf(v0.y, v1.y), fmaxf(v2.y, v3.y)),
                                     fmaxf(fmaxf(v4.y, v5.y), fmaxf(v6.y, v7.y))));
            mx.z = fmaxf(mx.z, fmaxf(fmaxf(fmaxf(v0.z, v1.z), fmaxf(v2.z, v3.z)),
                                     fmaxf(fmaxf(v4.z, v5.z), fmaxf(v6.z, v7.z))));
            mx.w = fmaxf(mx.w, fmaxf(fmaxf(fmaxf(v0.w, v1.w), fmaxf(v2.w, v3.w)),
                                     fmaxf(fmaxf(v4.w, v5.w), fmaxf(v6.w, v7.w))));
        }
        for (; l < e; ++l) {
            float4 v = hb[(size_t)l * H4];
            mx.x = fmaxf(mx.x, v.x); mx.y = fmaxf(mx.y, v.y);
            mx.z = fmaxf(mx.z, v.z); mx.w = fmaxf(mx.w, v.w);
        }
        rv = mx;
    }
    if (is_ent && t >= H4 && t < SPAN_PAD/4) {
        const int k = 4*t - HH;              // 0,4,...,28
        const float* se = size_emb + len*EE;
        rv.x = (k+0 < EE) ? se[k+0] : 0.f;
        rv.y = (k+1 < EE) ? se[k+1] : 0.f;
        rv.z = (k+2 < EE) ? se[k+2] : 0.f;
        rv.w = (k+3 < EE) ? se[k+3] : 0.f;
    }

    // ---- wait for weight transpose (overlapped with pooling above) ----
    if (t == 0) {
        volatile int* wd = &g_wdone;
        while (*wd < NTR) __nanosleep(32);
    }
    __syncthreads();
    __threadfence();   // acquire: order weight reads after observed release

    if (is_ent) {
        float acc[NROW];
        #pragma unroll
        for (int r = 0; r < NROW; ++r) acc[r] = 0.f;
        if (t < SPAN_PAD/4) {
            const float* wb = g_wentT + 4*t;
            #pragma unroll
            for (int r = 0; r < NROW; ++r) {
                float4 w = *reinterpret_cast<const float4*>(wb + r*SPAN_PAD);
                acc[r] = rv.x*w.x + rv.y*w.y + rv.z*w.z + rv.w*w.w;
            }
        }
        #pragma unroll
        for (int r = 0; r < NROW; ++r) {
            float v = acc[r];
            #pragma unroll
            for (int o = 16; o; o >>= 1) v += __shfl_down_sync(0xffffffffu, v, o);
            if (lane == 0) sred[warp][r] = v;
        }
        __syncthreads();
        if (t < NROW) {
            float s = 0.f;
            #pragma unroll
            for (int w = 0; w < 8; ++w) s += sred[w][t];
            if      (t < NEC)       out[idx*NEC + t]                = s + b_span[t];
            else if (t < NEC + NRC) g_p1[idx*NRC + (t - NEC)]       = s;
            else                    g_p2[idx*NRC + (t - NEC - NRC)] = s;
        }
    } else {
        float acc[NRC];
        #pragma unroll
        for (int r = 0; r < NRC; ++r) acc[r] = 0.f;
        if (t < H4) {
            const float* wb = g_wctxT + 4*t;
            #pragma unroll
            for (int r = 0; r < NRC; ++r) {
                float4 w = *reinterpret_cast<const float4*>(wb + r*HH);
                acc[r] = rv.x*w.x + rv.y*w.y + rv.z*w.z + rv.w*w.w;
            }
        }
        #pragma unroll
        for (int r = 0; r < NRC; ++r) {
            float v = acc[r];
            #pragma unroll
            for (int o = 16; o; o >>= 1) v += __shfl_down_sync(0xffffffffu, v, o);
            if (lane == 0) sred[warp][r] = v;
        }
        __syncthreads();
        if (t < NRC) {
            float s = 0.f;
            #pragma unroll
            for (int w = 0; w < 8; ++w) s += sred[w][t];
            g_pc[idx*NRC + t] = s;
        }
    }

    // ================= last-block-done combine =================
    __threadfence();
    __syncthreads();
    if (t == 0)
        s_last = (atomicAdd(&g_pdone, 1) == NPOOL - 1) ? 1 : 0;
    __syncthreads();

    if (s_last) {
        __threadfence();   // acquire: all p1/p2/pc visible
        for (int i = t; i < NREL*NRC; i += 256) {
            const int rid = i / NRC, j = i - rid*NRC;
            const int bb  = rid / RR;
            const int hi  = rel[rid*2 + 0];
            const int ti  = rel[rid*2 + 1];
            out[NENT*NEC + i] = g_pc[i]
                              + g_p1[(bb*SS + hi)*NRC + j]
                              + g_p2[(bb*SS + ti)*NRC + j]
                              + b_rel[j];
        }
        if (t == 0) { g_pdone = 0; g_wdone = 0; }   // reset for next graph replay
    }
}

// -----------------------------------------------------------------------------
// kernel_launch: inputs per metadata order:
//   0 hidden_states (f32)  1 entity_masks (i32)  2 relations (i32)
//   3 relation_context_masks (i32)  4 size_emb (f32)
//   5 w_span (f32)  6 b_span (f32)  7 w_rel (f32)  8 b_rel (f32)
// out: 6400 f32 = entity_logits (4000) ++ relation_logits (2400)
// -----------------------------------------------------------------------------
extern "C" void kernel_launch(void* const* d_in, const int* in_sizes, int n_in,
                              void* d_out, int out_size)
{
    const float* hid      = (const float*)d_in[0];
    const int*   emask    = (const int*)  d_in[1];
    const int*   rel      = (const int*)  d_in[2];
    const int*   cmask    = (const int*)  d_in[3];
    const float* size_emb = (const float*)d_in[4];
    const float* w_span   = (const float*)d_in[5];
    const float* b_span   = (const float*)d_in[6];
    const float* w_rel    = (const float*)d_in[7];
    const float* b_rel    = (const float*)d_in[8];
    float* out = (float*)d_out;

    spert_fused_kernel<<<GRID, 256>>>(hid, emask, rel, cmask, size_emb,
                                      w_span, b_span, w_rel, b_rel, out);
}

// round 11
// speedup vs baseline: 1.3907x; 1.3907x over previous
#include <cuda_runtime.h>
#include <cuda_bf16.h>

// Problem constants (fixed by the reference)
#define BB  4
#define LL  512
#define HH  768
#define SS  100
#define RR  100
#define EE  25
#define NEC 10              // entity classes
#define NRC 6               // relation classes
#define NEGV (-1e20f)

#define H4       (HH/4)         // 192 float4 lanes per hidden row
#define SPAN_DIM (HH + EE)      // 793
#define REL_DIM  (3*HH + 2*EE)  // 2354
#define SPAN_PAD 800            // padded (mult of 4), zero tail
#define REL_PAD  2368           // padded (mult of 4), zero tail
#define NENT     (BB*SS)        // 400
#define NREL     (BB*RR)        // 400

// Scratch (static device globals — no runtime allocation)
__device__ float g_ent[NENT*HH];              // pooled entity reprs
__device__ float g_esz[NENT*EE];              // entity size embeddings
__device__ float g_ctx[NREL*HH];              // pooled relation-context reprs
__device__ float g_wspanT[NEC*SPAN_PAD];      // w_span^T, rows padded+zeroed
__device__ float g_wrelT [NRC*REL_PAD];       // w_rel^T,  rows padded+zeroed

// -----------------------------------------------------------------------------
// Kernel A: pooling (blocks 0..799) + padded weight transpose (blocks 800..802)
// (unchanged from the measured-best R7 version)
// -----------------------------------------------------------------------------
__global__ void __launch_bounds__(256)
spert_pool_kernel(const float* __restrict__ hid,
                  const int*   __restrict__ emask,
                  const int*   __restrict__ cmask,
                  const float* __restrict__ size_emb,
                  const float* __restrict__ w_span,
                  const float* __restrict__ w_rel)
{
    const int bid = blockIdx.x;
    const int t   = threadIdx.x;

    // ---- weight transpose blocks (zero-padded rows) ----
    if (bid >= NENT + NREL) {
        int which = bid - (NENT + NREL);
        if (which == 0) {
            for (int i = t; i < NEC*SPAN_PAD; i += 256) {
                int j = i / SPAN_PAD, k = i - j*SPAN_PAD;
                g_wspanT[i] = (k < SPAN_DIM) ? w_span[k*NEC + j] : 0.f;
            }
        } else {
            int half = (NRC*REL_PAD) / 2;        // 7104
            int base = (which - 1) * half;
            for (int i = base + t; i < base + half; i += 256) {
                int j = i / REL_PAD, k = i - j*REL_PAD;
                g_wrelT[i] = (k < REL_DIM) ? w_rel[k*NRC + j] : 0.f;
            }
        }
        return;
    }

    __shared__ int s_start;
    const bool is_ent = (bid < NENT);
    const int idx  = is_ent ? bid : bid - NENT;   // b*N + n
    const int b    = idx / SS;
    const int lane = t & 31, warp = t >> 5;

    // ---- recover contiguous span (start, len): ballot min + syncthreads_count ----
    const int* mrow = (is_ent ? emask : cmask) + (size_t)idx * LL;
    const int m0 = mrow[t];
    const int m1 = mrow[t + 256];
    if (t == 0) s_start = LL;
    __syncthreads();
    unsigned bal0 = __ballot_sync(0xffffffffu, m0 != 0);
    unsigned bal1 = __ballot_sync(0xffffffffu, m1 != 0);
    if (lane == 0) {
        if (bal0) atomicMin(&s_start, (warp << 5) + __ffs(bal0) - 1);
        if (bal1) atomicMin(&s_start, 256 + (warp << 5) + __ffs(bal1) - 1);
    }
    const int len = __syncthreads_count(m0 != 0) + __syncthreads_count(m1 != 0);
    const int start = s_start;   // barrier above orders the atomics

    // ---- masked max pool over span (float4, unroll 4 for MLP) ----
    if (t < H4) {
        float4 mx = make_float4(NEGV, NEGV, NEGV, NEGV);
        const float4* hb = reinterpret_cast<const float4*>(hid + (size_t)b * LL * HH) + t;
        int l = start, e = start + len;
        for (; l + 4 <= e; l += 4) {
            float4 v0 = hb[(size_t)(l+0) * H4];
            float4 v1 = hb[(size_t)(l+1) * H4];
            float4 v2 = hb[(size_t)(l+2) * H4];
            float4 v3 = hb[(size_t)(l+3) * H4];
            mx.x = fmaxf(fmaxf(mx.x, v0.x), fmaxf(v1.x, fmaxf(v2.x, v3.x)));
            mx.y = fmaxf(fmaxf(mx.y, v0.y), fmaxf(v1.y, fmaxf(v2.y, v3.y)));
            mx.z = fmaxf(fmaxf(mx.z, v0.z), fmaxf(v1.z, fmaxf(v2.z, v3.z)));
            mx.w = fmaxf(fmaxf(mx.w, v0.w), fmaxf(v1.w, fmaxf(v2.w, v3.w)));
        }
        for (; l < e; ++l) {
            float4 v = hb[(size_t)l * H4];
            mx.x = fmaxf(mx.x, v.x); mx.y = fmaxf(mx.y, v.y);
            mx.z = fmaxf(mx.z, v.z); mx.w = fmaxf(mx.w, v.w);
        }
        float4* dst = reinterpret_cast<float4*>((is_ent ? g_ent : g_ctx) + (size_t)idx * HH);
        dst[t] = mx;
    }
    if (is_ent && t < EE)
        g_esz[idx*EE + t] = size_emb[len*EE + t];
}

// -----------------------------------------------------------------------------
// Kernel B: logits with 128-thread blocks (800 blocks -> ONE wave on 148 SMs).
// blocks 0..399 entity, 400..799 relation. Barrier-free float4 dots from
// padded transposed weights (L1-resident), 4-warp reduce.
// -----------------------------------------------------------------------------
__global__ void __launch_bounds__(128)
spert_logits_kernel(const int*   __restrict__ rel,
                    const float* __restrict__ b_span,
                    const float* __restrict__ b_rel,
                    float*       __restrict__ out)
{
    __shared__ float sred[4][NEC];
    const int bid  = blockIdx.x;
    const int t    = threadIdx.x;
    const int warp = t >> 5, lane = t & 31;

    if (bid < NENT) {
        // ===== entity logits: repr(793) @ w_span -> out[bid][0..10) =====
        const int idx = bid;
        const float4* ent4 = reinterpret_cast<const float4*>(g_ent + (size_t)idx * HH);
        const float*  esz  = g_esz + (size_t)idx * EE;

        // thread handles chunks c = t and t+128 (< 200)
        float4 rv0, rv1;
        {
            // chunk t < 128 is always hidden region
            rv0 = ent4[t];
            const int c1 = t + 128;
            if (c1 < H4) {
                rv1 = ent4[c1];
            } else {
                const int k = 4*c1 - HH;      // 0..
                rv1.x = (k+0 < EE) ? esz[k+0] : 0.f;
                rv1.y = (k+1 < EE) ? esz[k+1] : 0.f;
                rv1.z = (k+2 < EE) ? esz[k+2] : 0.f;
                rv1.w = (k+3 < EE) ? esz[k+3] : 0.f;
            }
        }
        const bool has1 = (t + 128) < SPAN_PAD/4;   // t < 72

        float acc[NEC];
        #pragma unroll
        for (int j = 0; j < NEC; ++j) {
            const float4 w0 = *reinterpret_cast<const float4*>(g_wspanT + j*SPAN_PAD + 4*t);
            float a = rv0.x*w0.x + rv0.y*w0.y + rv0.z*w0.z + rv0.w*w0.w;
            if (has1) {
                const float4 w1 = *reinterpret_cast<const float4*>(g_wspanT + j*SPAN_PAD + 4*(t+128));
                a += rv1.x*w1.x + rv1.y*w1.y + rv1.z*w1.z + rv1.w*w1.w;
            }
            acc[j] = a;
        }
        #pragma unroll
        for (int j = 0; j < NEC; ++j) {
            float v = acc[j];
            #pragma unroll
            for (int o = 16; o; o >>= 1) v += __shfl_down_sync(0xffffffffu, v, o);
            if (lane == 0) sred[warp][j] = v;
        }
        __syncthreads();
        if (t < NEC) {
            float s = sred[0][t] + sred[1][t] + sred[2][t] + sred[3][t];
            out[idx*NEC + t] = s + b_span[t];
        }
        return;
    }

    // ===== relation logits: [ctx|ent_h|ent_t|sz_h|sz_t](2354) @ w_rel =====
    const int idx = bid - NENT;          // b*R + r
    const int b   = idx / RR;
    const int hi  = rel[idx*2 + 0];      // issued first: longest dep chain
    const int ti  = rel[idx*2 + 1];

    const float4* ctx4 = reinterpret_cast<const float4*>(g_ctx + (size_t)idx * HH);
    const float4* eh4  = reinterpret_cast<const float4*>(g_ent + (size_t)(b*SS + hi) * HH);
    const float4* et4  = reinterpret_cast<const float4*>(g_ent + (size_t)(b*SS + ti) * HH);
    const float*  szh  = g_esz + (size_t)(b*SS + hi) * EE;
    const float*  szt  = g_esz + (size_t)(b*SS + ti) * EE;

    // chunks c = t + 128*i, i = 0..4  (REL_PAD/4 = 592 -> i=4 only for t<80)
    float4 rv[5];
    #pragma unroll
    for (int i = 0; i < 5; ++i) {
        const int c = t + 128*i;
        if (c < REL_PAD/4) {
            const int k = c << 2;
            if      (k < HH)    rv[i] = ctx4[c];
            else if (k < 2*HH)  rv[i] = eh4[c - H4];
            else if (k < 3*HH)  rv[i] = et4[c - 2*H4];
            else {
                float cc[4];
                #pragma unroll
                for (int q = 0; q < 4; ++q) {
                    int kk = k + q;
                    cc[q] = (kk < 3*HH + EE) ? szh[kk - 3*HH]
                          : (kk < REL_DIM)   ? szt[kk - 3*HH - EE]
                          : 0.f;
                }
                rv[i] = make_float4(cc[0], cc[1], cc[2], cc[3]);
            }
        } else {
            rv[i] = make_float4(0.f, 0.f, 0.f, 0.f);
        }
    }

    float acc[NRC];
    #pragma unroll
    for (int j = 0; j < NRC; ++j) {
        float a = 0.f;
        #pragma unroll
        for (int i = 0; i < 5; ++i) {
            const int c = t + 128*i;
            if (c < REL_PAD/4) {
                const float4 w = *reinterpret_cast<const float4*>(g_wrelT + j*REL_PAD + (c << 2));
                a += rv[i].x*w.x + rv[i].y*w.y + rv[i].z*w.z + rv[i].w*w.w;
            }
        }
        acc[j] = a;
    }
    #pragma unroll
    for (int j = 0; j < NRC; ++j) {
        float v = acc[j];
        #pragma unroll
        for (int o = 16; o; o >>= 1) v += __shfl_down_sync(0xffffffffu, v, o);
        if (lane == 0) sred[warp][j] = v;
    }
    __syncthreads();
    if (t < NRC) {
        float s = sred[0][t] + sred[1][t] + sred[2][t] + sred[3][t];
        out[NENT*NEC + idx*NRC + t] = s + b_rel[t];
    }
}

// -----------------------------------------------------------------------------
// kernel_launch: inputs per metadata order:
//   0 hidden_states (f32)  1 entity_masks (i32)  2 relations (i32)
//   3 relation_context_masks (i32)  4 size_emb (f32)
//   5 w_span (f32)  6 b_span (f32)  7 w_rel (f32)  8 b_rel (f32)
// out: 6400 f32 = entity_logits (4000) ++ relation_logits (2400)
// -----------------------------------------------------------------------------
extern "C" void kernel_launch(void* const* d_in, const int* in_sizes, int n_in,
                              void* d_out, int out_size)
{
    const float* hid      = (const float*)d_in[0];
    const int*   emask    = (const int*)  d_in[1];
    const int*   rel      = (const int*)  d_in[2];
    const int*   cmask    = (const int*)  d_in[3];
    const float* size_emb = (const float*)d_in[4];
    const float* w_span   = (const float*)d_in[5];
    const float* b_span   = (const float*)d_in[6];
    const float* w_rel    = (const float*)d_in[7];
    const float* b_rel    = (const float*)d_in[8];
    float* out = (float*)d_out;

    spert_pool_kernel<<<NENT + NREL + 3, 256>>>(hid, emask, cmask, size_emb,
                                                w_span, w_rel);
    spert_logits_kernel<<<NENT + NREL, 128>>>(rel, b_span, b_rel, out);
}